// round 3
// baseline (speedup 1.0000x reference)
#include <cuda_runtime.h>
#include <cuda_bf16.h>

// out[row] = (sum over 1024 elements of x[row,:]) * sum(coeffs)
// One warp per 4 consecutive rows. Per row: 32 lanes x 8 float4 (unrolled).
// Warp-shuffle reduce only; 4 independent reduce chains pipeline; one STG.128.
__global__ void __launch_bounds__(256) spline_rowsum_warp4_kernel(
        const float* __restrict__ x,
        const float* __restrict__ coeffs,
        int ncoef,
        int nwarp_groups,              // rows / 4
        float* __restrict__ out) {
    const int wg = (blockIdx.x * (blockDim.x >> 5)) + (threadIdx.x >> 5);
    if (wg >= nwarp_groups) return;
    const int lane = threadIdx.x & 31;

    // 4 rows x 256 float4 each, base of this warp's 4-row chunk
    const float4* __restrict__ xp =
        reinterpret_cast<const float4*>(x) + (size_t)wg * 1024 + lane;

    float rs[4];

    #pragma unroll
    for (int r = 0; r < 4; r++) {
        const float4* __restrict__ p = xp + r * 256;
        float4 v0 = p[0 * 32];
        float4 v1 = p[1 * 32];
        float4 v2 = p[2 * 32];
        float4 v3 = p[3 * 32];
        float4 v4 = p[4 * 32];
        float4 v5 = p[5 * 32];
        float4 v6 = p[6 * 32];
        float4 v7 = p[7 * 32];

        float s0 = (v0.x + v0.y) + (v0.z + v0.w);
        float s1 = (v1.x + v1.y) + (v1.z + v1.w);
        float s2 = (v2.x + v2.y) + (v2.z + v2.w);
        float s3 = (v3.x + v3.y) + (v3.z + v3.w);
        float s4 = (v4.x + v4.y) + (v4.z + v4.w);
        float s5 = (v5.x + v5.y) + (v5.z + v5.w);
        float s6 = (v6.x + v6.y) + (v6.z + v6.w);
        float s7 = (v7.x + v7.y) + (v7.z + v7.w);

        rs[r] = ((s0 + s1) + (s2 + s3)) + ((s4 + s5) + (s6 + s7));
    }

    // 4 independent shuffle-reduce chains (pipeline across chains)
    #pragma unroll
    for (int o = 16; o > 0; o >>= 1) {
        rs[0] += __shfl_xor_sync(0xffffffffu, rs[0], o);
        rs[1] += __shfl_xor_sync(0xffffffffu, rs[1], o);
        rs[2] += __shfl_xor_sync(0xffffffffu, rs[2], o);
        rs[3] += __shfl_xor_sync(0xffffffffu, rs[3], o);
    }

    if (lane == 0) {
        float cs = 0.0f;
        for (int i = 0; i < ncoef; i++) cs += coeffs[i];  // 10 elems, L2-hit
        float4 o4 = make_float4(rs[0] * cs, rs[1] * cs, rs[2] * cs, rs[3] * cs);
        reinterpret_cast<float4*>(out)[wg] = o4;          // 16B-aligned: wg*4 floats
    }
}

extern "C" void kernel_launch(void* const* d_in, const int* in_sizes, int n_in,
                              void* d_out, int out_size) {
    const float* x      = (const float*)d_in[0];
    const float* coeffs = (const float*)d_in[1];
    float*       out    = (float*)d_out;

    const int rows  = out_size;            // 65536
    const int ncoef = in_sizes[1];         // 10

    const int nwg = rows / 4;              // 16384 warp-groups
    const int warps_per_block = 8;         // 256 threads
    const int blocks = (nwg + warps_per_block - 1) / warps_per_block;  // 2048
    spline_rowsum_warp4_kernel<<<blocks, 256>>>(x, coeffs, ncoef, nwg, out);
}

// round 4
// speedup vs baseline: 1.0141x; 1.0141x over previous
#include <cuda_runtime.h>
#include <cuda_bf16.h>

// out[row] = (sum over 1024 elements of x[row,:]) * sum(coeffs)
// One warp per 2 rows, software-pipelined: row1's loads are in flight while
// row0's shuffle-reduce runs. Streaming loads (__ldcs) — data is read once.
__global__ void __launch_bounds__(256) spline_rowsum_pipe2_kernel(
        const float* __restrict__ x,
        const float* __restrict__ coeffs,
        int ncoef,
        int npairs,                    // rows / 2
        float* __restrict__ out) {
    const int wg = (blockIdx.x * (blockDim.x >> 5)) + (threadIdx.x >> 5);
    if (wg >= npairs) return;
    const int lane = threadIdx.x & 31;

    // 2 rows x 256 float4 each
    const float4* __restrict__ p0 =
        reinterpret_cast<const float4*>(x) + (size_t)wg * 512 + lane;
    const float4* __restrict__ p1 = p0 + 256;

    // ---- row 0: issue 8 streaming loads ----
    float4 a0 = __ldcs(p0 + 0 * 32);
    float4 a1 = __ldcs(p0 + 1 * 32);
    float4 a2 = __ldcs(p0 + 2 * 32);
    float4 a3 = __ldcs(p0 + 3 * 32);
    float4 a4 = __ldcs(p0 + 4 * 32);
    float4 a5 = __ldcs(p0 + 5 * 32);
    float4 a6 = __ldcs(p0 + 6 * 32);
    float4 a7 = __ldcs(p0 + 7 * 32);

    // reduce row 0 to one lane-local scalar
    float s0 = (((a0.x + a0.y) + (a0.z + a0.w)) + ((a1.x + a1.y) + (a1.z + a1.w)))
             + ((((a2.x + a2.y) + (a2.z + a2.w)) + ((a3.x + a3.y) + (a3.z + a3.w))));
    s0 += (((a4.x + a4.y) + (a4.z + a4.w)) + ((a5.x + a5.y) + (a5.z + a5.w)))
        + ((((a6.x + a6.y) + (a6.z + a6.w)) + ((a7.x + a7.y) + (a7.z + a7.w))));

    // ---- row 1: issue 8 streaming loads BEFORE row 0's shuffle tree ----
    float4 b0 = __ldcs(p1 + 0 * 32);
    float4 b1 = __ldcs(p1 + 1 * 32);
    float4 b2 = __ldcs(p1 + 2 * 32);
    float4 b3 = __ldcs(p1 + 3 * 32);
    float4 b4 = __ldcs(p1 + 4 * 32);
    float4 b5 = __ldcs(p1 + 5 * 32);
    float4 b6 = __ldcs(p1 + 6 * 32);
    float4 b7 = __ldcs(p1 + 7 * 32);

    // row 0 shuffle reduce overlaps with row 1 loads in flight
    #pragma unroll
    for (int o = 16; o > 0; o >>= 1)
        s0 += __shfl_xor_sync(0xffffffffu, s0, o);

    float s1 = (((b0.x + b0.y) + (b0.z + b0.w)) + ((b1.x + b1.y) + (b1.z + b1.w)))
             + ((((b2.x + b2.y) + (b2.z + b2.w)) + ((b3.x + b3.y) + (b3.z + b3.w))));
    s1 += (((b4.x + b4.y) + (b4.z + b4.w)) + ((b5.x + b5.y) + (b5.z + b5.w)))
        + ((((b6.x + b6.y) + (b6.z + b6.w)) + ((b7.x + b7.y) + (b7.z + b7.w))));

    #pragma unroll
    for (int o = 16; o > 0; o >>= 1)
        s1 += __shfl_xor_sync(0xffffffffu, s1, o);

    if (lane == 0) {
        float cs = 0.0f;
        for (int i = 0; i < ncoef; i++) cs += coeffs[i];  // 10 elems, L2-hit
        float2 o2 = make_float2(s0 * cs, s1 * cs);
        reinterpret_cast<float2*>(out)[wg] = o2;          // 8B-aligned
    }
}

extern "C" void kernel_launch(void* const* d_in, const int* in_sizes, int n_in,
                              void* d_out, int out_size) {
    const float* x      = (const float*)d_in[0];
    const float* coeffs = (const float*)d_in[1];
    float*       out    = (float*)d_out;

    const int rows   = out_size;           // 65536
    const int ncoef  = in_sizes[1];        // 10
    const int npairs = rows / 2;           // 32768 warps

    const int warps_per_block = 8;         // 256 threads
    const int blocks = (npairs + warps_per_block - 1) / warps_per_block;  // 4096
    spline_rowsum_pipe2_kernel<<<blocks, 256>>>(x, coeffs, ncoef, npairs, out);
}

// round 5
// speedup vs baseline: 1.0483x; 1.0337x over previous
#include <cuda_runtime.h>
#include <cuda_bf16.h>

// out[row] = (sum over 1024 elements of x[row,:]) * sum(coeffs)
// One warp per row: 32 lanes x 8 float4 loads (fully unrolled).
// __launch_bounds__(256, 6) -> ~42 regs/thread so all 8 float4 stay live
// (true MLP=8 per thread) at 48 warps/SM.
__global__ void __launch_bounds__(256, 6) spline_rowsum_mlp8_kernel(
        const float* __restrict__ x,
        const float* __restrict__ coeffs,
        int ncoef,
        int rows,
        float* __restrict__ out) {
    const int warp_global = (blockIdx.x * (blockDim.x >> 5)) + (threadIdx.x >> 5);
    const int lane = threadIdx.x & 31;

    const float4* __restrict__ xp =
        reinterpret_cast<const float4*>(x) + (size_t)warp_global * 256 + lane;

    // 8 independent 16B loads per lane — all live simultaneously
    float4 v0 = xp[0 * 32];
    float4 v1 = xp[1 * 32];
    float4 v2 = xp[2 * 32];
    float4 v3 = xp[3 * 32];
    float4 v4 = xp[4 * 32];
    float4 v5 = xp[5 * 32];
    float4 v6 = xp[6 * 32];
    float4 v7 = xp[7 * 32];

    float s0 = (v0.x + v0.y) + (v0.z + v0.w);
    float s1 = (v1.x + v1.y) + (v1.z + v1.w);
    float s2 = (v2.x + v2.y) + (v2.z + v2.w);
    float s3 = (v3.x + v3.y) + (v3.z + v3.w);
    float s4 = (v4.x + v4.y) + (v4.z + v4.w);
    float s5 = (v5.x + v5.y) + (v5.z + v5.w);
    float s6 = (v6.x + v6.y) + (v6.z + v6.w);
    float s7 = (v7.x + v7.y) + (v7.z + v7.w);

    float s = ((s0 + s1) + (s2 + s3)) + ((s4 + s5) + (s6 + s7));

    #pragma unroll
    for (int o = 16; o > 0; o >>= 1)
        s += __shfl_xor_sync(0xffffffffu, s, o);

    if (lane == 0) {
        float cs = 0.0f;
        for (int i = 0; i < ncoef; i++) cs += coeffs[i];  // 10 elems, L2-hit
        out[warp_global] = s * cs;
    }
}

extern "C" void kernel_launch(void* const* d_in, const int* in_sizes, int n_in,
                              void* d_out, int out_size) {
    const float* x      = (const float*)d_in[0];
    const float* coeffs = (const float*)d_in[1];
    float*       out    = (float*)d_out;

    const int rows  = out_size;            // 65536 (divides 8 exactly)
    const int ncoef = in_sizes[1];         // 10

    const int warps_per_block = 8;         // 256 threads
    const int blocks = rows / warps_per_block;  // 8192
    spline_rowsum_mlp8_kernel<<<blocks, 256>>>(x, coeffs, ncoef, rows, out);
}

// round 6
// speedup vs baseline: 1.0548x; 1.0062x over previous
#include <cuda_runtime.h>
#include <cuda_bf16.h>

// out[row] = (sum over 1024 elements of x[row,:]) * sum(coeffs)
// One warp per 2 rows. ALL 16 float4 loads (8 KB/warp) issued up front
// before any reduction -> per-warp 16 outstanding LDG.128.
// __launch_bounds__(256,3): <=85 regs so all 16 float4 stay live.
__global__ void __launch_bounds__(256, 3) spline_rowsum_batch16_kernel(
        const float* __restrict__ x,
        const float* __restrict__ coeffs,
        int ncoef,
        float* __restrict__ out) {
    const int wg   = (blockIdx.x * (blockDim.x >> 5)) + (threadIdx.x >> 5);
    const int lane = threadIdx.x & 31;

    // 2 rows x 256 float4
    const float4* __restrict__ p =
        reinterpret_cast<const float4*>(x) + (size_t)wg * 512 + lane;

    // ---- issue all 16 loads before any consumption ----
    float4 a0 = p[0 * 32];
    float4 a1 = p[1 * 32];
    float4 a2 = p[2 * 32];
    float4 a3 = p[3 * 32];
    float4 a4 = p[4 * 32];
    float4 a5 = p[5 * 32];
    float4 a6 = p[6 * 32];
    float4 a7 = p[7 * 32];
    float4 b0 = p[8 * 32];
    float4 b1 = p[9 * 32];
    float4 b2 = p[10 * 32];
    float4 b3 = p[11 * 32];
    float4 b4 = p[12 * 32];
    float4 b5 = p[13 * 32];
    float4 b6 = p[14 * 32];
    float4 b7 = p[15 * 32];

    float s0 = ((((a0.x + a0.y) + (a0.z + a0.w)) + ((a1.x + a1.y) + (a1.z + a1.w)))
             +  (((a2.x + a2.y) + (a2.z + a2.w)) + ((a3.x + a3.y) + (a3.z + a3.w))))
             + ((((a4.x + a4.y) + (a4.z + a4.w)) + ((a5.x + a5.y) + (a5.z + a5.w)))
             +  (((a6.x + a6.y) + (a6.z + a6.w)) + ((a7.x + a7.y) + (a7.z + a7.w))));

    float s1 = ((((b0.x + b0.y) + (b0.z + b0.w)) + ((b1.x + b1.y) + (b1.z + b1.w)))
             +  (((b2.x + b2.y) + (b2.z + b2.w)) + ((b3.x + b3.y) + (b3.z + b3.w))))
             + ((((b4.x + b4.y) + (b4.z + b4.w)) + ((b5.x + b5.y) + (b5.z + b5.w)))
             +  (((b6.x + b6.y) + (b6.z + b6.w)) + ((b7.x + b7.y) + (b7.z + b7.w))));

    // two independent shuffle chains (pipeline)
    #pragma unroll
    for (int o = 16; o > 0; o >>= 1) {
        s0 += __shfl_xor_sync(0xffffffffu, s0, o);
        s1 += __shfl_xor_sync(0xffffffffu, s1, o);
    }

    if (lane == 0) {
        float cs = 0.0f;
        for (int i = 0; i < ncoef; i++) cs += coeffs[i];  // 10 elems, L2-hit
        reinterpret_cast<float2*>(out)[wg] = make_float2(s0 * cs, s1 * cs);
    }
}

extern "C" void kernel_launch(void* const* d_in, const int* in_sizes, int n_in,
                              void* d_out, int out_size) {
    const float* x      = (const float*)d_in[0];
    const float* coeffs = (const float*)d_in[1];
    float*       out    = (float*)d_out;

    const int rows   = out_size;           // 65536
    const int ncoef  = in_sizes[1];        // 10
    const int npairs = rows / 2;           // 32768 warps

    const int warps_per_block = 8;         // 256 threads
    const int blocks = npairs / warps_per_block;  // 4096
    spline_rowsum_batch16_kernel<<<blocks, 256>>>(x, coeffs, ncoef, out);
}